// round 1
// baseline (speedup 1.0000x reference)
#include <cuda_runtime.h>

// RetNet retention: per-channel decay scan.
// B=4, S=4096, D=2048, H=16, hd=128. decay[h] broadcast per head.
// Chunked scan: 64 chunks of length 64 along S.
//   K1: per-chunk aggregate A_c = sum_i d^{L-1-i} * k_i*v_i   (Horner)
//   K2: in-place exclusive scan over chunks: carry_c = d^L*carry_{c-1} + A_{c-1}
//   K3: r = carry_c; r = d*r + k*v; out = q*r

#define B_ 4
#define S_ 4096
#define D_ 2048
#define H_ 16
#define HD_ 128        // channels per head
#define NCHUNK 64
#define CLEN 64        // S_/NCHUNK
#define D4 (D_/4)      // 512 float4 groups per row

// Scratch: chunk aggregates, then (after K2) exclusive carries. 2 MB.
__device__ float4 g_state[B_ * NCHUNK * D4];

__global__ void __launch_bounds__(128) k_chunk_agg(
    const float4* __restrict__ kk_, const float4* __restrict__ vv_,
    const float* __restrict__ decay)
{
    const int c4    = blockIdx.x * 128 + threadIdx.x;   // 0..D4-1
    const int chunk = blockIdx.y;
    const int b     = blockIdx.z;
    const float d   = decay[(c4 * 4) / HD_];

    size_t base = ((size_t)(b * S_ + chunk * CLEN)) * D4 + c4;
    float4 a = make_float4(0.f, 0.f, 0.f, 0.f);

    #pragma unroll 8
    for (int i = 0; i < CLEN; ++i) {
        float4 kk = kk_[base + (size_t)i * D4];
        float4 vv = vv_[base + (size_t)i * D4];
        a.x = fmaf(a.x, d, kk.x * vv.x);
        a.y = fmaf(a.y, d, kk.y * vv.y);
        a.z = fmaf(a.z, d, kk.z * vv.z);
        a.w = fmaf(a.w, d, kk.w * vv.w);
    }
    g_state[(b * NCHUNK + chunk) * D4 + c4] = a;
}

__global__ void __launch_bounds__(128) k_scan_carries(
    const float* __restrict__ decay)
{
    const int c4 = blockIdx.x * 128 + threadIdx.x;      // 0..D4-1
    const int b  = blockIdx.y;
    const float d  = decay[(c4 * 4) / HD_];
    const float dL = powf(d, (float)CLEN);              // d^64 ~ 1.2e-3, fine in fp32

    float4 prev = make_float4(0.f, 0.f, 0.f, 0.f);
    for (int c = 0; c < NCHUNK; ++c) {
        const int idx = (b * NCHUNK + c) * D4 + c4;
        float4 a = g_state[idx];
        g_state[idx] = prev;                            // exclusive carry for chunk c
        prev.x = fmaf(prev.x, dL, a.x);
        prev.y = fmaf(prev.y, dL, a.y);
        prev.z = fmaf(prev.z, dL, a.z);
        prev.w = fmaf(prev.w, dL, a.w);
    }
}

__global__ void __launch_bounds__(128) k_apply(
    const float4* __restrict__ qq_, const float4* __restrict__ kk_,
    const float4* __restrict__ vv_, const float* __restrict__ decay,
    float4* __restrict__ out)
{
    const int c4    = blockIdx.x * 128 + threadIdx.x;
    const int chunk = blockIdx.y;
    const int b     = blockIdx.z;
    const float d   = decay[(c4 * 4) / HD_];

    float4 r = g_state[(b * NCHUNK + chunk) * D4 + c4];
    size_t base = ((size_t)(b * S_ + chunk * CLEN)) * D4 + c4;

    #pragma unroll 8
    for (int i = 0; i < CLEN; ++i) {
        const size_t off = base + (size_t)i * D4;
        float4 kk = kk_[off];
        float4 vv = vv_[off];
        float4 qq = qq_[off];
        r.x = fmaf(r.x, d, kk.x * vv.x);
        r.y = fmaf(r.y, d, kk.y * vv.y);
        r.z = fmaf(r.z, d, kk.z * vv.z);
        r.w = fmaf(r.w, d, kk.w * vv.w);
        float4 o;
        o.x = qq.x * r.x;
        o.y = qq.y * r.y;
        o.z = qq.z * r.z;
        o.w = qq.w * r.w;
        out[off] = o;
    }
}

extern "C" void kernel_launch(void* const* d_in, const int* in_sizes, int n_in,
                              void* d_out, int out_size)
{
    (void)in_sizes; (void)n_in; (void)out_size;
    const float4* q     = (const float4*)d_in[0];
    const float4* k     = (const float4*)d_in[1];
    const float4* v     = (const float4*)d_in[2];
    const float*  decay = (const float*)d_in[3];
    float4* out = (float4*)d_out;

    dim3 grid(D4 / 128, NCHUNK, B_);     // (4, 64, 4) blocks of 128
    k_chunk_agg<<<grid, 128>>>(k, v, decay);

    dim3 grid2(D4 / 128, B_);            // (4, 4) blocks of 128
    k_scan_carries<<<grid2, 128>>>(decay);

    k_apply<<<grid, 128>>>(q, k, v, decay, out);
}

// round 2
// speedup vs baseline: 1.0026x; 1.0026x over previous
#include <cuda_runtime.h>

// RetNet retention, single-pass chunked scan with decoupled lookback.
// B=4, S=4096, D=2048 (512 float4 channels), H=16 (32 float4/head).
// Chains: (b, channel-block-of-128-float4) -> 16 chains, 256 chunks of 16 steps.
// item = ticket; chunk = item>>4, chain = item&15  => pred(item) = item-16.

#define S_ 4096
#define D4 512
#define CLEN 16
#define NITEM 4096   // 256 chunks * 16 chains

__device__ float4   g_agg [NITEM * 128];
__device__ float4   g_pref[NITEM * 128];
__device__ int      g_flags[NITEM];
__device__ unsigned g_ticket;

__global__ void k_reset()
{
    int i = blockIdx.x * 1024 + threadIdx.x;
    if (i < NITEM) g_flags[i] = 0;
    if (i == 0)    g_ticket = 0;
}

__global__ void __launch_bounds__(128, 8) k_scan(
    const float4* __restrict__ q, const float4* __restrict__ k,
    const float4* __restrict__ v, const float* __restrict__ decay,
    float4* __restrict__ out)
{
    __shared__ unsigned s_item;
    __shared__ int s_f;
    const int tid = threadIdx.x;

    if (tid == 0) s_item = atomicAdd(&g_ticket, 1u);
    __syncthreads();
    const unsigned item = s_item;
    const int chunk = item >> 4;
    const int chain = item & 15;
    const int b     = chain >> 2;
    const int cblk  = chain & 3;
    const int c4    = cblk * 128 + tid;

    const float d  = decay[c4 >> 5];          // 32 float4 per head
    const float d2 = d * d, dq = d2 * d2, d8 = dq * dq, dL = d8 * d8; // d^16

    const size_t base = ((size_t)b * S_ + (size_t)chunk * CLEN) * D4 + c4;

    // ---- phase 1: chunk aggregate A = sum_i d^{CLEN-1-i} k_i v_i (Horner) ----
    float4 a = make_float4(0.f, 0.f, 0.f, 0.f);
    #pragma unroll
    for (int i = 0; i < CLEN; ++i) {
        float4 kk = k[base + (size_t)i * D4];
        float4 vv = v[base + (size_t)i * D4];
        a.x = fmaf(a.x, d, kk.x * vv.x);
        a.y = fmaf(a.y, d, kk.y * vv.y);
        a.z = fmaf(a.z, d, kk.z * vv.z);
        a.w = fmaf(a.w, d, kk.w * vv.w);
    }
    __stcg(&g_agg[item * 128 + tid], a);
    __syncthreads();
    if (tid == 0) { __threadfence(); atomicExch(&g_flags[item], 1); }

    // ---- phase 2: lookback for exclusive carry E ----
    float4 E = make_float4(0.f, 0.f, 0.f, 0.f);
    if (chunk > 0) {
        float coef = 1.f;
        int p = (int)item - 16;
        for (;;) {
            if (tid == 0) {
                int f;
                do { f = *(volatile int*)&g_flags[p]; } while (f == 0);
                s_f = f;
            }
            __syncthreads();
            const int f = s_f;
            __threadfence();
            const float4 w = (f == 2) ? __ldcg(&g_pref[p * 128 + tid])
                                      : __ldcg(&g_agg [p * 128 + tid]);
            E.x = fmaf(coef, w.x, E.x);
            E.y = fmaf(coef, w.y, E.y);
            E.z = fmaf(coef, w.z, E.z);
            E.w = fmaf(coef, w.w, E.w);
            __syncthreads();                    // protect s_f reuse
            if (f == 2 || p < 16) break;        // prefix found, or pred is chunk 0
            coef *= dL;
            p -= 16;
        }
    }

    // ---- publish inclusive prefix I = d^CLEN * E + A ----
    float4 I;
    I.x = fmaf(dL, E.x, a.x);
    I.y = fmaf(dL, E.y, a.y);
    I.z = fmaf(dL, E.z, a.z);
    I.w = fmaf(dL, E.w, a.w);
    __stcg(&g_pref[item * 128 + tid], I);
    __syncthreads();
    if (tid == 0) { __threadfence(); atomicExch(&g_flags[item], 2); }

    // ---- phase 3: apply recurrence from carry, write out ----
    // k,v re-read should hit L2 (read moments ago); q/out streamed (no L2 pollution).
    float4 r = E;
    #pragma unroll
    for (int i = 0; i < CLEN; ++i) {
        const size_t off = base + (size_t)i * D4;
        float4 kk = k[off];
        float4 vv = v[off];
        float4 qq = __ldcs(&q[off]);
        r.x = fmaf(r.x, d, kk.x * vv.x);
        r.y = fmaf(r.y, d, kk.y * vv.y);
        r.z = fmaf(r.z, d, kk.z * vv.z);
        r.w = fmaf(r.w, d, kk.w * vv.w);
        float4 o;
        o.x = qq.x * r.x;
        o.y = qq.y * r.y;
        o.z = qq.z * r.z;
        o.w = qq.w * r.w;
        __stcs(&out[off], o);
    }
}

extern "C" void kernel_launch(void* const* d_in, const int* in_sizes, int n_in,
                              void* d_out, int out_size)
{
    (void)in_sizes; (void)n_in; (void)out_size;
    const float4* q     = (const float4*)d_in[0];
    const float4* k     = (const float4*)d_in[1];
    const float4* v     = (const float4*)d_in[2];
    const float*  decay = (const float*)d_in[3];
    float4* out = (float4*)d_out;

    k_reset<<<4, 1024>>>();
    k_scan<<<NITEM, 128>>>(q, k, v, decay, out);
}